// round 10
// baseline (speedup 1.0000x reference)
#include <cuda_runtime.h>
#include <cstdint>

// Problem constants
#define NB    32
#define CH    64
#define HH    112
#define WW    112
#define HWSZ  (HH*WW)            // 12544
#define PIX   (NB*HWSZ)          // 401408
#define ELEMS (NB*CH*HWSZ)       // 25690112
#define NW    576
#define EPSV  1e-5
#define HP    114                // padded height
#define WPD   114                // padded width
#define NTILE (NB*HH)            // 3584 row-tiles

// ---- device scratch (no allocations allowed) ----
__device__ signed char g_xpad[(size_t)NB*HP*WPD*CH];   // +-1/0 s8 padded image, 26.6 MB
__device__ signed char g_wb[9*CH*CH];                  // +-1 s8 weights [tap][oc][ch]
__device__ float       g_scale[CH];
__device__ long long   g_S1[CH], g_S2[CH];
__device__ short       g_sint[ELEMS];                  // conv integer results (NCHW)

// ---- k2 SMEM layout (byte offsets into dynamic smem) ----
// A: 3 image rows x 114 px, pitch 80 B/px  (px data = 64 ch bytes)  -> 27360 B
// B: 9 taps x 64 oc, pitch 80 B/oc        (oc data = 64 ch bytes)  -> 46080 B
// OUT staging (aliases A after sync): 64 oc x pitch 240 B (112 shorts used)
#define A_PITCH   80u
#define A_ROW     (114u*A_PITCH)     // 9120
#define B_OFFB    27360u
#define B_TAP     (64u*A_PITCH)      // 5120
#define OUT_PITCH 240u               // 16-byte aligned pitch (fix for R7 fault)
#define SMEM_K2   73472

__device__ __forceinline__ uint32_t smem_u32(const void* p) {
    uint32_t a;
    asm("{ .reg .u64 t; cvta.to.shared.u64 t, %1; cvt.u32.u64 %0, t; }" : "=r"(a) : "l"(p));
    return a;
}
__device__ __forceinline__ void ldsm4(uint32_t a, uint32_t& r0, uint32_t& r1, uint32_t& r2, uint32_t& r3) {
    asm volatile("ldmatrix.sync.aligned.m8n8.x4.shared.b16 {%0,%1,%2,%3}, [%4];"
                 : "=r"(r0), "=r"(r1), "=r"(r2), "=r"(r3) : "r"(a));
}
__device__ __forceinline__ void imma(int* d, uint32_t a0, uint32_t a1, uint32_t a2, uint32_t a3,
                                     uint32_t b0, uint32_t b1) {
    asm volatile("mma.sync.aligned.m16n8k32.row.col.s32.s8.s8.s32 "
                 "{%0,%1,%2,%3}, {%4,%5,%6,%7}, {%8,%9}, {%0,%1,%2,%3};"
                 : "+r"(d[0]), "+r"(d[1]), "+r"(d[2]), "+r"(d[3])
                 : "r"(a0), "r"(a1), "r"(a2), "r"(a3), "r"(b0), "r"(b1));
}
__device__ __forceinline__ void sts128(uint32_t a, uint4 v) {
    asm volatile("st.shared.v4.b32 [%0],{%1,%2,%3,%4};" :: "r"(a), "r"(v.x), "r"(v.y), "r"(v.z), "r"(v.w));
}
__device__ __forceinline__ void sts16(uint32_t a, uint32_t h) {
    asm volatile("st.shared.u16 [%0],%1;" :: "r"(a), "r"(h));
}
__device__ __forceinline__ uint32_t lds32(uint32_t a) {
    uint32_t v; asm volatile("ld.shared.b32 %0,[%1];" : "=r"(v) : "r"(a)); return v;
}
__device__ __forceinline__ uint4 lds128(uint32_t a) {
    uint4 v;
    asm volatile("ld.shared.v4.b32 {%0,%1,%2,%3},[%4];"
                 : "=r"(v.x), "=r"(v.y), "=r"(v.z), "=r"(v.w) : "r"(a));
    return v;
}

// ---------------------------------------------------------------------------
// K0: weight signs -> s8 +-1 [tap][oc][ch]; per-channel mean|w|; zero stats.
// ---------------------------------------------------------------------------
__global__ void k0_prep(const float* __restrict__ wflat) {
    __shared__ float abss[NW];
    int t = threadIdx.x;           // 0..575
    int o = t / 9, tap = t % 9;
    float asum = 0.0f;
    #pragma unroll 8
    for (int i = 0; i < CH; i++) {
        float w = wflat[(o * CH + i) * 9 + tap];
        asum += fabsf(w);
        g_wb[tap * (CH * CH) + o * CH + i] = (__float_as_uint(w) >> 31) ? (signed char)-1 : (signed char)1;
    }
    abss[t] = asum;
    __syncthreads();
    if (t < CH) {
        float s = 0.0f;
        #pragma unroll
        for (int j = 0; j < 9; j++) s += abss[t * 9 + j];
        g_scale[t] = s * (1.0f / (float)NW);
        g_S1[t] = 0ll;
        g_S2[t] = 0ll;
    }
}

// ---------------------------------------------------------------------------
// K1: build padded +-1/0 s8 NHWC image. One block per padded row (n, hp).
// ---------------------------------------------------------------------------
__global__ void __launch_bounds__(256) k1_pack(const float* __restrict__ x) {
    __shared__ unsigned int sb[WW * 16];            // 112 px x 64 ch bytes (as 16 u32)
    int b  = blockIdx.x;                            // 0..NB*HP-1
    int n  = b / HP, hp = b % HP;
    uint4* dst = (uint4*)(g_xpad + (size_t)(n * HP + hp) * WPD * CH);  // 456 uint4

    if (hp == 0 || hp == HP - 1) {
        uint4 z = make_uint4(0, 0, 0, 0);
        for (int j = threadIdx.x; j < 456; j += 256) dst[j] = z;
        return;
    }
    int h = hp - 1;
    const float* xb = x + (size_t)n * CH * HWSZ + h * WW;
    #pragma unroll
    for (int it = 0; it < 7; it++) {
        int idx = it * 256 + threadIdx.x;           // 0..1791
        int w  = idx % WW;
        int cg = idx / WW;                          // 0..15
        unsigned int v = 0;
        #pragma unroll
        for (int k = 0; k < 4; k++) {
            unsigned int u = __float_as_uint(xb[(size_t)(cg * 4 + k) * HWSZ + w]);
            unsigned int byte = (u >> 31) ? 0xFFu : 0x01u;
            v |= byte << (k * 8);
        }
        sb[w * 16 + cg] = v;
    }
    __syncthreads();
    uint4 z = make_uint4(0, 0, 0, 0);
    for (int j = threadIdx.x; j < 456; j += 256) {
        int px = j >> 2, q = j & 3;
        dst[j] = (px == 0 || px == WPD - 1) ? z : *(uint4*)&sb[(px - 1) * 16 + q * 4];
    }
}

// ---------------------------------------------------------------------------
// K2: persistent IMMA binary conv. 296 CTAs (2/SM) x 224 threads (7 warps).
// Tile = one image row: M=112 px (7 warps x 16), N=64 oc, K=64ch x 9 taps.
// ---------------------------------------------------------------------------
__global__ void __launch_bounds__(224, 2) k2_imma(void) {
    extern __shared__ char sm[];
    uint32_t base = smem_u32(sm);

    int tid  = threadIdx.x;
    int wi   = tid >> 5;
    int lane = tid & 31;

    // ---- load B once: [9][64 oc][64 ch] -> pitch 80 ----
    for (int j = tid; j < 2304; j += 224) {         // 2304 uint4 = 36864 B
        int tap = j >> 8, oc = (j >> 2) & 63, q = j & 3;
        uint4 v = *(const uint4*)(g_wb + tap * (CH * CH) + oc * CH + q * 16);
        sts128(base + B_OFFB + tap * B_TAP + oc * A_PITCH + q * 16u, v);
    }

    // per-lane fragment base addresses
    uint32_t a_base = base + (uint32_t)((wi * 16 + (lane & 15)) * A_PITCH) + ((lane & 16) ? 16u : 0u);
    uint32_t b_base = base + B_OFFB
                    + (uint32_t)((((lane & 16) >> 1) + (lane & 7)) * A_PITCH)
                    + ((lane & 8) ? 16u : 0u);

    int   sum1 = 0;
    long long sum2 = 0;
    __syncthreads();

    for (int t = blockIdx.x; t < NTILE; t += 296) {
        int n = t / HH, h = t % HH;

        // ---- stage A: padded rows h..h+2, 114 px x 64 B -> pitch 80 ----
        const signed char* src = g_xpad + (size_t)(n * HP + h) * WPD * CH;
        for (int j = tid; j < 1368; j += 224) {     // 1368 uint4 = 3*114*64 B
            int px = j >> 2, q = j & 3;             // px 0..341
            int r = px / WPD, col = px % WPD;
            uint4 v = *(const uint4*)(src + (size_t)(r * WPD + col) * CH + q * 16);
            sts128(base + r * A_ROW + col * A_PITCH + q * 16u, v);
        }
        __syncthreads();

        // ---- compute: 9 taps x 2 ksteps, 8 n-tiles ----
        int d[8][4];
        #pragma unroll
        for (int i = 0; i < 8; i++) { d[i][0] = d[i][1] = d[i][2] = d[i][3] = 0; }

        for (int tap = 0; tap < 9; tap++) {
            int dh = tap / 3, dw = tap % 3;
            uint32_t ab = a_base + dh * A_ROW + dw * A_PITCH;
            uint32_t bb = b_base + tap * B_TAP;
            #pragma unroll
            for (int ks = 0; ks < 2; ks++) {
                uint32_t a0, a1, a2, a3;
                ldsm4(ab + ks * 32, a0, a1, a2, a3);
                #pragma unroll
                for (int j = 0; j < 4; j++) {
                    uint32_t b0, b1, b2, b3;
                    ldsm4(bb + j * (16u * A_PITCH) + ks * 32, b0, b1, b2, b3);
                    imma(d[2 * j],     a0, a1, a2, a3, b0, b1);
                    imma(d[2 * j + 1], a0, a1, a2, a3, b2, b3);
                }
            }
        }
        __syncthreads();   // all A/B reads done; reuse A region for out staging

        // ---- stage D -> SMEM shorts [oc][px], pitch 240 ----
        {
            int r0 = wi * 16 + (lane >> 2);
            int c0 = (lane & 3) * 2;
            #pragma unroll
            for (int nt = 0; nt < 8; nt++) {
                int oc = nt * 8 + c0;
                sts16(base + oc * OUT_PITCH + r0 * 2,             (uint32_t)(unsigned short)(short)d[nt][0]);
                sts16(base + (oc + 1) * OUT_PITCH + r0 * 2,       (uint32_t)(unsigned short)(short)d[nt][1]);
                sts16(base + oc * OUT_PITCH + (r0 + 8) * 2,       (uint32_t)(unsigned short)(short)d[nt][2]);
                sts16(base + (oc + 1) * OUT_PITCH + (r0 + 8) * 2, (uint32_t)(unsigned short)(short)d[nt][3]);
            }
        }
        __syncthreads();

        // ---- stats (exact ints), one oc per thread<64 ----
        if (tid < CH) {
            #pragma unroll 8
            for (int j = 0; j < 56; j++) {
                uint32_t v = lds32(base + (uint32_t)tid * OUT_PITCH + j * 4);
                int a = (short)(v & 0xFFFF);
                int b = (short)(v >> 16);
                sum1 += a + b;
                sum2 += (long long)(a * a + b * b);
            }
        }
        // ---- coalesced g_sint stores: 64 oc x 14 uint4 ----
        {
            size_t rowbase = (size_t)n * CH * HWSZ + (size_t)h * WW;
            for (int j = tid; j < 896; j += 224) {
                int oc = j / 14, q = j % 14;
                uint4 v = lds128(base + (uint32_t)oc * OUT_PITCH + q * 16);
                *(uint4*)(g_sint + rowbase + (size_t)oc * HWSZ + q * 8) = v;
            }
        }
        __syncthreads();   // out region (A alias) free for next staging
    }

    if (tid < CH) {
        atomicAdd((unsigned long long*)&g_S1[tid], (unsigned long long)(long long)sum1);
        atomicAdd((unsigned long long*)&g_S2[tid], (unsigned long long)sum2);
    }
}

// ---------------------------------------------------------------------------
// K4: BN fold (per-block preamble, exact double) + elementwise epilogue
//     out = s*A[o] + B[o] + x.  8 elems/iter x 8 iters, streaming hints.
// ---------------------------------------------------------------------------
__global__ void __launch_bounds__(256) k4_epilogue(
    const float* __restrict__ x, const float* __restrict__ gamma,
    const float* __restrict__ beta, float* __restrict__ out)
{
    __shared__ float sA[CH], sB[CH];
    int tid = threadIdx.x;
    if (tid < CH) {
        const double cnt = (double)PIX;
        double sc   = (double)g_scale[tid];
        double mean = sc * ((double)g_S1[tid] / cnt);
        double ex2  = sc * sc * ((double)g_S2[tid] / cnt);
        double var  = ex2 - mean * mean;
        double inv  = (double)gamma[tid] * rsqrt(var + EPSV);
        sA[tid] = (float)(sc * inv);
        sB[tid] = (float)((double)beta[tid] - mean * inv);
    }
    __syncthreads();

    int base = blockIdx.x * 2048;                  // ELEMS/8 = 3211264 = 1568*2048
    #pragma unroll 4
    for (int it = 0; it < 8; it++) {
        int i = base + it * 256 + tid;             // 8-elem group
        int o = (i / (HWSZ / 8)) & (CH - 1);
        float a = sA[o], b = sB[o];
        int4  sv = __ldcs((const int4*)g_sint + i);
        float4 x0 = __ldcs((const float4*)x + 2 * i);
        float4 x1 = __ldcs((const float4*)x + 2 * i + 1);
        short2 s0 = *(short2*)&sv.x, s1 = *(short2*)&sv.y;
        short2 s2 = *(short2*)&sv.z, s3 = *(short2*)&sv.w;
        float4 r0, r1;
        r0.x = fmaf((float)s0.x, a, b) + x0.x;
        r0.y = fmaf((float)s0.y, a, b) + x0.y;
        r0.z = fmaf((float)s1.x, a, b) + x0.z;
        r0.w = fmaf((float)s1.y, a, b) + x0.w;
        r1.x = fmaf((float)s2.x, a, b) + x1.x;
        r1.y = fmaf((float)s2.y, a, b) + x1.y;
        r1.z = fmaf((float)s3.x, a, b) + x1.z;
        r1.w = fmaf((float)s3.y, a, b) + x1.w;
        __stcs((float4*)out + 2 * i, r0);
        __stcs((float4*)out + 2 * i + 1, r1);
    }
}

// ---------------------------------------------------------------------------
extern "C" void kernel_launch(void* const* d_in, const int* in_sizes, int n_in,
                              void* d_out, int out_size) {
    const float* x     = (const float*)d_in[0];
    const float* wts   = (const float*)d_in[1];
    const float* gamma = (const float*)d_in[2];
    const float* beta  = (const float*)d_in[3];
    float* out = (float*)d_out;

    cudaFuncSetAttribute(k2_imma, cudaFuncAttributeMaxDynamicSharedMemorySize, SMEM_K2);

    k0_prep<<<1, NW>>>(wts);
    k1_pack<<<NB * HP, 256>>>(x);
    k2_imma<<<296, 224, SMEM_K2>>>();
    k4_epilogue<<<1568, 256>>>(x, gamma, beta, out);
}

// round 11
// speedup vs baseline: 2.0335x; 2.0335x over previous
#include <cuda_runtime.h>
#include <cstdint>

// Problem constants
#define NB   32
#define CH   64
#define HH   112
#define WW   112
#define HWSZ (HH*WW)             // 12544
#define PIX  (NB*HWSZ)           // 401408
#define ELEMS (NB*CH*HWSZ)       // 25690112
#define NW   576
#define EPSV 1e-5

// Scratch (device globals only)
__device__ unsigned long long g_xbits[PIX];          // packed activation signs
__device__ unsigned long long g_wpad[CH*10];         // packed weight signs, padded 10/channel
__device__ unsigned char      g_popcw[NW];           // popc per weight word
__device__ short              g_cs[16*CH];           // border correction per pattern x channel
__device__ float              g_scale[CH];           // mean |w| per output channel
__device__ long long          g_S1[CH];              // exact sum of s
__device__ long long          g_S2[CH];              // exact sum of s^2
__device__ short              g_sint[ELEMS];         // conv integer results (NCHW)

// ---------------------------------------------------------------------------
// K0a: weight packing. 1 block, 576 threads. Packs signs (padded 10/channel),
// per-channel mean|w|, popc table, zeroes stat accumulators.
// ---------------------------------------------------------------------------
__global__ void k0a_pack_w(const float* __restrict__ wflat) {
    __shared__ float abss[NW];
    int t = threadIdx.x;           // 0..575
    int o = t / 9, tap = t % 9;
    unsigned long long bits = 0ull;
    float asum = 0.0f;
    #pragma unroll 8
    for (int i = 0; i < CH; i++) {
        float w = wflat[(o * CH + i) * 9 + tap];
        bits |= (unsigned long long)(__float_as_uint(w) >> 31) << i;
        asum += fabsf(w);
    }
    g_wpad[o * 10 + tap] = bits;
    g_popcw[t] = (unsigned char)__popcll(bits);
    abss[t] = asum;
    __syncthreads();
    if (t < CH) {
        float s = 0.0f;
        #pragma unroll
        for (int j = 0; j < 9; j++) s += abss[t * 9 + j];
        g_scale[t] = s * (1.0f / (float)NW);
        g_S1[t] = 0ll;
        g_S2[t] = 0ll;
        g_wpad[t * 10 + 9] = 0ull;   // padding slot
    }
}

// ---------------------------------------------------------------------------
// K0b: border-correction table (reads g_popcw, written by k0a earlier in the
// stream). 1 block, 256 threads, 4 entries each.
// pattern bit0=top(h==0), 1=bottom(h==111), 2=left(w==0), 3=right(w==111)
// ---------------------------------------------------------------------------
__global__ void k0b_cs(void) {
    __shared__ unsigned char wps[NW];
    int t = threadIdx.x;
    for (int j = t; j < NW; j += 256) wps[j] = g_popcw[j];
    __syncthreads();
    for (int idx = t; idx < 16 * CH; idx += 256) {
        int p = idx >> 6, o2 = idx & 63;
        unsigned m = 0;
        if (p & 1) m |= 0x007;   // taps 0,1,2
        if (p & 2) m |= 0x1C0;   // taps 6,7,8
        if (p & 4) m |= 0x049;   // taps 0,3,6
        if (p & 8) m |= 0x124;   // taps 2,5,8
        int c = 0;
        while (m) { int tt = __ffs(m) - 1; m &= m - 1; c += wps[o2 * 9 + tt]; }
        g_cs[idx] = (short)c;
    }
}

// ---------------------------------------------------------------------------
// K1: pack sign bits of x. 4 pixels per thread, float4 loads per channel.
// ---------------------------------------------------------------------------
__global__ void __launch_bounds__(256) k1_pack(const float* __restrict__ x) {
    int t  = blockIdx.x * 256 + threadIdx.x;       // PIX/4 threads exactly
    int pb = t * 4;
    int n  = pb / HWSZ;
    int hw = pb % HWSZ;                            // HWSZ%4==0 -> same n for all 4
    const float* xp = x + (size_t)n * CH * HWSZ + hw;
    unsigned long long b0 = 0, b1 = 0, b2 = 0, b3 = 0;
    #pragma unroll 8
    for (int c = 0; c < CH; c++) {
        float4 v = *(const float4*)(xp + (size_t)c * HWSZ);
        b0 |= (unsigned long long)(__float_as_uint(v.x) >> 31) << c;
        b1 |= (unsigned long long)(__float_as_uint(v.y) >> 31) << c;
        b2 |= (unsigned long long)(__float_as_uint(v.z) >> 31) << c;
        b3 |= (unsigned long long)(__float_as_uint(v.w) >> 31) << c;
    }
    ulonglong2* dst = (ulonglong2*)(g_xbits + pb);
    dst[0] = make_ulonglong2(b0, b1);
    dst[1] = make_ulonglong2(b2, b3);
}

// ---------------------------------------------------------------------------
// K2: binary conv via xor+popc (R2 version — measured best). One thread per
// pixel, all 64 output channels; branch-free border handling via cs table.
// ---------------------------------------------------------------------------
__global__ void __launch_bounds__(256) k2_conv(void) {
    __shared__ __align__(16) unsigned long long ws[CH * 10];
    __shared__ short cs_s[16 * CH];
    __shared__ int bs1[CH], bs2[CH];

    int tid = threadIdx.x;
    #pragma unroll
    for (int j = tid; j < CH * 10; j += 256) ws[j] = g_wpad[j];
    #pragma unroll
    for (int j = tid; j < 16 * CH; j += 256) cs_s[j] = g_cs[j];
    if (tid < CH) { bs1[tid] = 0; bs2[tid] = 0; }
    __syncthreads();

    int p  = blockIdx.x * 256 + tid;               // 401408 = 1568*256
    int n  = p / HWSZ;
    int hw = p % HWSZ;
    int h  = hw / WW;
    int w  = hw % WW;

    int pat = (h == 0) | ((h == HH - 1) << 1) | ((w == 0) << 2) | ((w == WW - 1) << 3);

    unsigned long long xb[9];
    const unsigned long long* xrow = g_xbits + (size_t)n * HWSZ;
    #pragma unroll
    for (int dh = -1; dh <= 1; dh++) {
        #pragma unroll
        for (int dw = -1; dw <= 1; dw++) {
            int t2 = (dh + 1) * 3 + (dw + 1);
            int hh = h + dh, w2 = w + dw;
            bool valid = (hh >= 0) & (hh < HH) & (w2 >= 0) & (w2 < WW);
            xb[t2] = valid ? xrow[hh * WW + w2] : 0ull;
        }
    }
    int nv64 = 64 * (9 - (!!(pat & 1) + !!(pat & 2) + !!(pat & 4) + !!(pat & 8)) * 3
                       + ((pat & 1) && (pat & 4)) + ((pat & 1) && (pat & 8))
                       + ((pat & 2) && (pat & 4)) + ((pat & 2) && (pat & 8)));
    const short* csrow = cs_s + (pat << 6);
    size_t obase = (size_t)n * CH * HWSZ + hw;
    int lane0 = ((tid & 31) == 0);

    #pragma unroll 2
    for (int o = 0; o < CH; o++) {
        const ulonglong2* wv = (const ulonglong2*)(ws + o * 10);
        ulonglong2 w01 = wv[0], w23 = wv[1], w45 = wv[2], w67 = wv[3];
        unsigned long long w8 = ws[o * 10 + 8];
        int acc = __popcll(xb[0] ^ w01.x) + __popcll(xb[1] ^ w01.y)
                + __popcll(xb[2] ^ w23.x) + __popcll(xb[3] ^ w23.y)
                + __popcll(xb[4] ^ w45.x) + __popcll(xb[5] ^ w45.y)
                + __popcll(xb[6] ^ w67.x) + __popcll(xb[7] ^ w67.y)
                + __popcll(xb[8] ^ w8);
        int s = nv64 - 2 * acc + 2 * (int)csrow[o];
        g_sint[obase + (size_t)o * HWSZ] = (short)s;

        int s1 = __reduce_add_sync(0xffffffffu, s);
        int s2 = __reduce_add_sync(0xffffffffu, s * s);
        if (lane0) { atomicAdd(&bs1[o], s1); atomicAdd(&bs2[o], s2); }
    }
    __syncthreads();
    if (tid < CH) {
        atomicAdd((unsigned long long*)&g_S1[tid], (unsigned long long)(long long)bs1[tid]);
        atomicAdd((unsigned long long*)&g_S2[tid], (unsigned long long)(long long)bs2[tid]);
    }
}

// ---------------------------------------------------------------------------
// K4: BN fold (per-block preamble, exact double) + elementwise epilogue
//     out = s*A[o] + B[o] + x.  8 elems/iter x 4 iters, streaming hints.
// ---------------------------------------------------------------------------
__global__ void __launch_bounds__(256) k4_epilogue(
    const float* __restrict__ x, const float* __restrict__ gamma,
    const float* __restrict__ beta, float* __restrict__ out)
{
    __shared__ float sA[CH], sB[CH];
    int tid = threadIdx.x;
    if (tid < CH) {
        const double cnt = (double)PIX;
        double sc   = (double)g_scale[tid];
        double mean = sc * ((double)g_S1[tid] / cnt);
        double ex2  = sc * sc * ((double)g_S2[tid] / cnt);
        double var  = ex2 - mean * mean;
        double inv  = (double)gamma[tid] * rsqrt(var + EPSV);
        sA[tid] = (float)(sc * inv);
        sB[tid] = (float)((double)beta[tid] - mean * inv);
    }
    __syncthreads();

    int base = blockIdx.x * 1024;                  // ELEMS/8 = 3211264 = 3136*1024
    #pragma unroll 4
    for (int it = 0; it < 4; it++) {
        int i = base + it * 256 + tid;             // 8-elem group
        int o = (i / (HWSZ / 8)) & (CH - 1);
        float a = sA[o], b = sB[o];
        int4  sv = __ldcs((const int4*)g_sint + i);
        float4 x0 = __ldcs((const float4*)x + 2 * i);
        float4 x1 = __ldcs((const float4*)x + 2 * i + 1);
        short2 s0 = *(short2*)&sv.x, s1 = *(short2*)&sv.y;
        short2 s2 = *(short2*)&sv.z, s3 = *(short2*)&sv.w;
        float4 r0, r1;
        r0.x = fmaf((float)s0.x, a, b) + x0.x;
        r0.y = fmaf((float)s0.y, a, b) + x0.y;
        r0.z = fmaf((float)s1.x, a, b) + x0.z;
        r0.w = fmaf((float)s1.y, a, b) + x0.w;
        r1.x = fmaf((float)s2.x, a, b) + x1.x;
        r1.y = fmaf((float)s2.y, a, b) + x1.y;
        r1.z = fmaf((float)s3.x, a, b) + x1.z;
        r1.w = fmaf((float)s3.y, a, b) + x1.w;
        __stcs((float4*)out + 2 * i, r0);
        __stcs((float4*)out + 2 * i + 1, r1);
    }
}

// ---------------------------------------------------------------------------
// Launch order puts k2 in the 4th slot — the slot the profiler has captured in
// every round so far — to finally get k2's roofline.
// ---------------------------------------------------------------------------
extern "C" void kernel_launch(void* const* d_in, const int* in_sizes, int n_in,
                              void* d_out, int out_size) {
    const float* x     = (const float*)d_in[0];
    const float* wts   = (const float*)d_in[1];
    const float* gamma = (const float*)d_in[2];
    const float* beta  = (const float*)d_in[3];
    float* out = (float*)d_out;

    k0a_pack_w<<<1, NW>>>(wts);
    k1_pack<<<PIX / 4 / 256, 256>>>(x);
    k0b_cs<<<1, 256>>>();
    k2_conv<<<PIX / 256, 256>>>();
    k4_epilogue<<<3136, 256>>>(x, gamma, beta, out);
}